// round 1
// baseline (speedup 1.0000x reference)
#include <cuda_runtime.h>

#define HID 128
#define MAXN 50176
#define MAXE 1605632

__device__ __align__(16) float g_h[(size_t)MAXN * HID];
__device__ __align__(16) float g_acc[(size_t)MAXN * HID];
__device__ float g_si[MAXN];
__device__ float g_sj[MAXN];
__device__ float g_cnt[MAXN];
__device__ int   g_src[MAXE];
__device__ int   g_dst[MAXE];
__device__ int   g_is64;

// ---------------------------------------------------------------------------
// Edge-index dtype detection: if stored as int64 (little-endian, values in
// [0, 50000)), every odd int32 word in the first 2E int32s is a zero high
// word. If int32, odd words are random node ids (all-zero prob ~0).
// ---------------------------------------------------------------------------
__global__ void detect64_kernel(const int* __restrict__ p, int twoE) {
    __shared__ int any_nonzero;
    if (threadIdx.x == 0) any_nonzero = 0;
    __syncthreads();
    int local = 0;
    int half = twoE >> 1;
    for (int i = threadIdx.x; i < 4096; i += blockDim.x) {
        long long q = (long long)i * half / 4096;
        long long idx = 2 * q + 1;
        if (idx < twoE) local |= p[idx];
    }
    if (local) atomicOr(&any_nonzero, 1);
    __syncthreads();
    if (threadIdx.x == 0) g_is64 = (any_nonzero == 0) ? 1 : 0;
}

__global__ void convert_edges_kernel(const int* __restrict__ p, int E) {
    int e = blockIdx.x * blockDim.x + threadIdx.x;
    if (e >= E) return;
    if (g_is64) {
        g_src[e] = p[2 * e];
        g_dst[e] = p[2 * E + 2 * e];
    } else {
        g_src[e] = p[e];
        g_dst[e] = p[E + e];
    }
}

// ---------------------------------------------------------------------------
// Encoder GEMM: g_h = relu(x[M,256] @ W[256,128] + b[128])
// 128x128 block tile, BK=16, 256 threads, 8x8 per-thread micro-tile.
// ---------------------------------------------------------------------------
__global__ void gemm_relu_kernel(const float* __restrict__ A,
                                 const float* __restrict__ W,
                                 const float* __restrict__ bias,
                                 int M) {
    const int K = 256;
    __shared__ float As[16][132];   // transposed A tile, padded
    __shared__ float Bs[16][128];

    int tid = threadIdx.x;
    int tx = tid % 16;
    int ty = tid / 16;
    int block_m = blockIdx.x * 128;

    float acc[8][8];
#pragma unroll
    for (int i = 0; i < 8; i++)
#pragma unroll
        for (int j = 0; j < 8; j++) acc[i][j] = 0.f;

    for (int k0 = 0; k0 < K; k0 += 16) {
        // Load A tile: 128 rows x 16 cols = 512 float4
        for (int t = tid; t < 512; t += 256) {
            int r  = t >> 2;
            int c4 = t & 3;
            int row = block_m + r;
            float4 v = make_float4(0.f, 0.f, 0.f, 0.f);
            if (row < M)
                v = *(const float4*)(A + (size_t)row * K + k0 + c4 * 4);
            As[c4 * 4 + 0][r] = v.x;
            As[c4 * 4 + 1][r] = v.y;
            As[c4 * 4 + 2][r] = v.z;
            As[c4 * 4 + 3][r] = v.w;
        }
        // Load B tile: 16 rows x 128 cols = 512 float4
        for (int t = tid; t < 512; t += 256) {
            int r  = t >> 5;
            int c4 = t & 31;
            float4 v = *(const float4*)(W + (size_t)(k0 + r) * 128 + c4 * 4);
            *(float4*)&Bs[r][c4 * 4] = v;
        }
        __syncthreads();
#pragma unroll
        for (int k = 0; k < 16; k++) {
            float a[8], b[8];
#pragma unroll
            for (int i = 0; i < 8; i++) a[i] = As[k][ty * 8 + i];
#pragma unroll
            for (int j = 0; j < 8; j++) b[j] = Bs[k][tx * 8 + j];
#pragma unroll
            for (int i = 0; i < 8; i++)
#pragma unroll
                for (int j = 0; j < 8; j++) acc[i][j] += a[i] * b[j];
        }
        __syncthreads();
    }

#pragma unroll
    for (int i = 0; i < 8; i++) {
        int row = block_m + ty * 8 + i;
        if (row >= M) continue;
#pragma unroll
        for (int j = 0; j < 8; j++) {
            int col = tx * 8 + j;
            float v = acc[i][j] + bias[col];
            g_h[(size_t)row * HID + col] = v > 0.f ? v : 0.f;
        }
    }
}

// ---------------------------------------------------------------------------
// Per-node attention scalars: si = h . w[0:128], sj = h . w[128:256]
// One warp per node.
// ---------------------------------------------------------------------------
__global__ void dots_kernel(const float* __restrict__ w, int n) {
    int warp = (blockIdx.x * blockDim.x + threadIdx.x) >> 5;
    int lane = threadIdx.x & 31;
    if (warp >= n) return;
    float4 hv = ((const float4*)g_h)[(size_t)warp * 32 + lane];
    float4 wi = ((const float4*)w)[lane];
    float4 wj = ((const float4*)w)[32 + lane];
    float si = hv.x * wi.x + hv.y * wi.y + hv.z * wi.z + hv.w * wi.w;
    float sj = hv.x * wj.x + hv.y * wj.y + hv.z * wj.z + hv.w * wj.w;
#pragma unroll
    for (int o = 16; o; o >>= 1) {
        si += __shfl_xor_sync(0xFFFFFFFFu, si, o);
        sj += __shfl_xor_sync(0xFFFFFFFFu, sj, o);
    }
    if (lane == 0) { g_si[warp] = si; g_sj[warp] = sj; }
}

__global__ void zero_cnt_kernel(int n) {
    int i = blockIdx.x * blockDim.x + threadIdx.x;
    if (i < n) g_cnt[i] = 0.f;
}

__global__ void zero_acc_kernel(int total) {
    int i = blockIdx.x * blockDim.x + threadIdx.x;
    if (i < total) g_acc[i] = 0.f;
}

__global__ void counts_kernel(int E) {
    int e = blockIdx.x * blockDim.x + threadIdx.x;
    if (e < E) atomicAdd(&g_cnt[g_dst[e]], 1.0f);
}

// ---------------------------------------------------------------------------
// Edge aggregation: one warp per edge.
// alpha = sigmoid(si[dst] + sj[src] + b); acc[dst] += alpha * h[src]
// Scatter uses vectorized red.global.add.v4.f32 (sm_90+).
// ---------------------------------------------------------------------------
__global__ void edge_agg_kernel(const float* __restrict__ bptr, int E) {
    int e = (blockIdx.x * blockDim.x + threadIdx.x) >> 5;
    int lane = threadIdx.x & 31;
    if (e >= E) return;
    int s = g_src[e];
    int d = g_dst[e];
    float z = g_si[d] + g_sj[s] + bptr[0];
    float alpha = 1.0f / (1.0f + __expf(-z));
    float4 v = ((const float4*)(g_h + (size_t)s * HID))[lane];
    float* addr = g_acc + (size_t)d * HID + lane * 4;
    asm volatile("red.global.add.v4.f32 [%0], {%1,%2,%3,%4};"
                 :: "l"(addr),
                    "f"(v.x * alpha), "f"(v.y * alpha),
                    "f"(v.z * alpha), "f"(v.w * alpha)
                 : "memory");
}

// h = relu(acc / max(cnt,1))
__global__ void finalize_relu_kernel(int n) {
    int i = blockIdx.x * blockDim.x + threadIdx.x;
    if (i >= n * HID) return;
    int node = i >> 7;
    float c = g_cnt[node];
    c = c < 1.f ? 1.f : c;
    float v = g_acc[i] / c;
    g_h[i] = v > 0.f ? v : 0.f;
}

// out = (acc / max(cnt,1)) @ cls_w[128,2] + cls_b[2]; one warp per node.
__global__ void finalize_cls_kernel(const float* __restrict__ clsw,
                                    const float* __restrict__ clsb,
                                    float* __restrict__ out, int n) {
    int warp = (blockIdx.x * blockDim.x + threadIdx.x) >> 5;
    int lane = threadIdx.x & 31;
    if (warp >= n) return;
    float c = g_cnt[warp];
    c = c < 1.f ? 1.f : c;
    float inv = 1.0f / c;
    float4 v = ((const float4*)g_acc)[(size_t)warp * 32 + lane];
    v.x *= inv; v.y *= inv; v.z *= inv; v.w *= inv;
    int j = lane * 4;
    float o0 = v.x * clsw[(j + 0) * 2] + v.y * clsw[(j + 1) * 2] +
               v.z * clsw[(j + 2) * 2] + v.w * clsw[(j + 3) * 2];
    float o1 = v.x * clsw[(j + 0) * 2 + 1] + v.y * clsw[(j + 1) * 2 + 1] +
               v.z * clsw[(j + 2) * 2 + 1] + v.w * clsw[(j + 3) * 2 + 1];
#pragma unroll
    for (int o = 16; o; o >>= 1) {
        o0 += __shfl_xor_sync(0xFFFFFFFFu, o0, o);
        o1 += __shfl_xor_sync(0xFFFFFFFFu, o1, o);
    }
    if (lane == 0) {
        out[(size_t)warp * 2 + 0] = o0 + clsb[0];
        out[(size_t)warp * 2 + 1] = o1 + clsb[1];
    }
}

// ---------------------------------------------------------------------------
extern "C" void kernel_launch(void* const* d_in, const int* in_sizes, int n_in,
                              void* d_out, int out_size) {
    const float* x      = (const float*)d_in[0];
    const int*   ei     = (const int*)  d_in[1];
    const float* enc_w  = (const float*)d_in[2];
    const float* enc_b  = (const float*)d_in[3];
    const float* att1_w = (const float*)d_in[4];
    const float* att1_b = (const float*)d_in[5];
    const float* att2_w = (const float*)d_in[6];
    const float* att2_b = (const float*)d_in[7];
    const float* cls_w  = (const float*)d_in[8];
    const float* cls_b  = (const float*)d_in[9];
    float* out = (float*)d_out;

    int N = in_sizes[0] / 256;
    int E = in_sizes[1] / 2;

    // Decode edge indices (dtype-robust)
    detect64_kernel<<<1, 1024>>>(ei, 2 * E);
    convert_edges_kernel<<<(E + 255) / 256, 256>>>(ei, E);

    // Encoder
    gemm_relu_kernel<<<(N + 127) / 128, 256>>>(x, enc_w, enc_b, N);

    // Degree counts (shared across both layers)
    zero_cnt_kernel<<<(N + 255) / 256, 256>>>(N);
    counts_kernel<<<(E + 255) / 256, 256>>>(E);

    int total = N * HID;
    int edge_blocks = (E + 7) / 8;      // warp per edge, 8 warps/block
    int node_warp_blocks = (N + 7) / 8; // warp per node

    // Layer 1
    dots_kernel<<<node_warp_blocks, 256>>>(att1_w, N);
    zero_acc_kernel<<<(total + 255) / 256, 256>>>(total);
    edge_agg_kernel<<<edge_blocks, 256>>>(att1_b, E);
    finalize_relu_kernel<<<(total + 255) / 256, 256>>>(N);

    // Layer 2
    dots_kernel<<<node_warp_blocks, 256>>>(att2_w, N);
    zero_acc_kernel<<<(total + 255) / 256, 256>>>(total);
    edge_agg_kernel<<<edge_blocks, 256>>>(att2_b, E);
    finalize_cls_kernel<<<node_warp_blocks, 256>>>(cls_w, cls_b, out, N);
}

// round 2
// speedup vs baseline: 1.6104x; 1.6104x over previous
#include <cuda_runtime.h>

#define HID 128
#define MAXN 50176
#define MAXE 1605632

__device__ __align__(16) float g_h [(size_t)MAXN * HID];
__device__ __align__(16) float g_hb[(size_t)MAXN * HID];
__device__ float g_si[MAXN];
__device__ float g_sj[MAXN];
__device__ int   g_deg[MAXN];
__device__ int   g_start[MAXN];
__device__ int   g_cursor[MAXN];
__device__ int   g_src[MAXE];
__device__ int   g_dst[MAXE];
__device__ int   g_sorted[MAXE];   // src ids grouped by dst (CSR adjacency)
__device__ int   g_is64;

// ---------------------------------------------------------------------------
// Edge-index dtype detection: int64 little-endian values < 50000 have all-zero
// odd 32-bit words; int32 edge data does not.
// ---------------------------------------------------------------------------
__global__ void detect64_kernel(const int* __restrict__ p, int twoE) {
    __shared__ int any_nonzero;
    if (threadIdx.x == 0) any_nonzero = 0;
    __syncthreads();
    int local = 0;
    int half = twoE >> 1;
    for (int i = threadIdx.x; i < 4096; i += blockDim.x) {
        long long q = (long long)i * half / 4096;
        long long idx = 2 * q + 1;
        if (idx < twoE) local |= p[idx];
    }
    if (local) atomicOr(&any_nonzero, 1);
    __syncthreads();
    if (threadIdx.x == 0) g_is64 = (any_nonzero == 0) ? 1 : 0;
}

__global__ void convert_edges_kernel(const int* __restrict__ p, int E) {
    int e = blockIdx.x * blockDim.x + threadIdx.x;
    if (e >= E) return;
    if (g_is64) {
        g_src[e] = p[2 * e];
        g_dst[e] = p[2 * E + 2 * e];
    } else {
        g_src[e] = p[e];
        g_dst[e] = p[E + e];
    }
}

// ---------------------------------------------------------------------------
// CSR build: histogram -> exclusive scan -> cursor scatter
// ---------------------------------------------------------------------------
__global__ void zero_deg_kernel(int n) {
    int i = blockIdx.x * blockDim.x + threadIdx.x;
    if (i < n) g_deg[i] = 0;
}

__global__ void hist_kernel(int E) {
    int e = blockIdx.x * blockDim.x + threadIdx.x;
    if (e < E) atomicAdd(&g_deg[g_dst[e]], 1);
}

// Single-block exclusive scan over n bins (1024 threads, chunked).
__global__ void scan_kernel(int n) {
    __shared__ int warp_tot[32];
    __shared__ int carry_s;
    int tid = threadIdx.x;
    int lane = tid & 31;
    int wid = tid >> 5;
    if (tid == 0) carry_s = 0;
    __syncthreads();
    for (int base = 0; base < n; base += 1024) {
        int i = base + tid;
        int v = (i < n) ? g_deg[i] : 0;
        int x = v;
#pragma unroll
        for (int o = 1; o < 32; o <<= 1) {
            int y = __shfl_up_sync(0xFFFFFFFFu, x, o);
            if (lane >= o) x += y;
        }
        if (lane == 31) warp_tot[wid] = x;
        __syncthreads();
        if (wid == 0) {
            int t = warp_tot[lane];
#pragma unroll
            for (int o = 1; o < 32; o <<= 1) {
                int y = __shfl_up_sync(0xFFFFFFFFu, t, o);
                if (lane >= o) t += y;
            }
            warp_tot[lane] = t;
        }
        __syncthreads();
        int warp_off = wid ? warp_tot[wid - 1] : 0;
        int incl = x + warp_off;
        int c = carry_s;
        if (i < n) g_start[i] = c + incl - v;
        __syncthreads();
        if (tid == 1023) carry_s = c + incl;
        __syncthreads();
    }
}

__global__ void init_cursor_kernel(int n) {
    int i = blockIdx.x * blockDim.x + threadIdx.x;
    if (i < n) g_cursor[i] = g_start[i];
}

__global__ void scatter_kernel(int E) {
    int e = blockIdx.x * blockDim.x + threadIdx.x;
    if (e >= E) return;
    int d = g_dst[e];
    int pos = atomicAdd(&g_cursor[d], 1);
    g_sorted[pos] = g_src[e];
}

// ---------------------------------------------------------------------------
// Encoder GEMM: g_h = relu(x[M,256] @ W[256,128] + b[128])
// ---------------------------------------------------------------------------
__global__ void __launch_bounds__(256) gemm_relu_kernel(
        const float* __restrict__ A, const float* __restrict__ W,
        const float* __restrict__ bias, int M) {
    const int K = 256;
    __shared__ float As[16][132];
    __shared__ float Bs[16][128];

    int tid = threadIdx.x;
    int tx = tid % 16;
    int ty = tid / 16;
    int block_m = blockIdx.x * 128;

    float acc[8][8];
#pragma unroll
    for (int i = 0; i < 8; i++)
#pragma unroll
        for (int j = 0; j < 8; j++) acc[i][j] = 0.f;

    for (int k0 = 0; k0 < K; k0 += 16) {
        for (int t = tid; t < 512; t += 256) {
            int r  = t >> 2;
            int c4 = t & 3;
            int row = block_m + r;
            float4 v = make_float4(0.f, 0.f, 0.f, 0.f);
            if (row < M)
                v = *(const float4*)(A + (size_t)row * K + k0 + c4 * 4);
            As[c4 * 4 + 0][r] = v.x;
            As[c4 * 4 + 1][r] = v.y;
            As[c4 * 4 + 2][r] = v.z;
            As[c4 * 4 + 3][r] = v.w;
        }
        for (int t = tid; t < 512; t += 256) {
            int r  = t >> 5;
            int c4 = t & 31;
            float4 v = *(const float4*)(W + (size_t)(k0 + r) * 128 + c4 * 4);
            *(float4*)&Bs[r][c4 * 4] = v;
        }
        __syncthreads();
#pragma unroll
        for (int k = 0; k < 16; k++) {
            float a[8], b[8];
#pragma unroll
            for (int i = 0; i < 8; i++) a[i] = As[k][ty * 8 + i];
#pragma unroll
            for (int j = 0; j < 8; j++) b[j] = Bs[k][tx * 8 + j];
#pragma unroll
            for (int i = 0; i < 8; i++)
#pragma unroll
                for (int j = 0; j < 8; j++) acc[i][j] += a[i] * b[j];
        }
        __syncthreads();
    }

#pragma unroll
    for (int i = 0; i < 8; i++) {
        int row = block_m + ty * 8 + i;
        if (row >= M) continue;
#pragma unroll
        for (int j = 0; j < 8; j++) {
            int col = tx * 8 + j;
            float v = acc[i][j] + bias[col];
            g_h[(size_t)row * HID + col] = v > 0.f ? v : 0.f;
        }
    }
}

// ---------------------------------------------------------------------------
// Per-node attention scalars from h (useB selects g_hb): si=h.w[:128], sj=h.w[128:]
// ---------------------------------------------------------------------------
__global__ void dots_kernel(const float* __restrict__ w, int n, int useB) {
    int warp = (blockIdx.x * blockDim.x + threadIdx.x) >> 5;
    int lane = threadIdx.x & 31;
    if (warp >= n) return;
    const float4* hp = (const float4*)(useB ? g_hb : g_h);
    float4 hv = hp[(size_t)warp * 32 + lane];
    float4 wi = ((const float4*)w)[lane];
    float4 wj = ((const float4*)w)[32 + lane];
    float si = hv.x * wi.x + hv.y * wi.y + hv.z * wi.z + hv.w * wi.w;
    float sj = hv.x * wj.x + hv.y * wj.y + hv.z * wj.z + hv.w * wj.w;
#pragma unroll
    for (int o = 16; o; o >>= 1) {
        si += __shfl_xor_sync(0xFFFFFFFFu, si, o);
        sj += __shfl_xor_sync(0xFFFFFFFFu, sj, o);
    }
    if (lane == 0) { g_si[warp] = si; g_sj[warp] = sj; }
}

// ---------------------------------------------------------------------------
// Layer 1: warp per node; acc = sum_e sigmoid(si[d]+sj[s]+b)*h[s];
// g_hb[d] = relu(acc / max(deg,1))
// ---------------------------------------------------------------------------
__global__ void agg1_kernel(const float* __restrict__ bptr, int n) {
    int d = (blockIdx.x * blockDim.x + threadIdx.x) >> 5;
    int lane = threadIdx.x & 31;
    if (d >= n) return;
    int k0 = g_start[d];
    int deg = g_deg[d];
    float si = g_si[d];
    float b = bptr[0];
    float ax = 0.f, ay = 0.f, az = 0.f, aw = 0.f;
#pragma unroll 4
    for (int k = k0; k < k0 + deg; k++) {
        int s = g_sorted[k];
        float z = si + g_sj[s] + b;
        float alpha = 1.0f / (1.0f + __expf(-z));
        float4 v = ((const float4*)(g_h + (size_t)s * HID))[lane];
        ax += alpha * v.x; ay += alpha * v.y;
        az += alpha * v.z; aw += alpha * v.w;
    }
    float inv = 1.0f / (float)(deg < 1 ? 1 : deg);
    float4 o;
    o.x = ax * inv; o.y = ay * inv; o.z = az * inv; o.w = aw * inv;
    o.x = o.x > 0.f ? o.x : 0.f;
    o.y = o.y > 0.f ? o.y : 0.f;
    o.z = o.z > 0.f ? o.z : 0.f;
    o.w = o.w > 0.f ? o.w : 0.f;
    ((float4*)(g_hb + (size_t)d * HID))[lane] = o;
}

// ---------------------------------------------------------------------------
// Layer 2 + classifier fused: warp per node; v = acc/max(deg,1);
// out[d] = v @ cls_w + cls_b
// ---------------------------------------------------------------------------
__global__ void agg2_cls_kernel(const float* __restrict__ bptr,
                                const float* __restrict__ clsw,
                                const float* __restrict__ clsb,
                                float* __restrict__ out, int n) {
    int d = (blockIdx.x * blockDim.x + threadIdx.x) >> 5;
    int lane = threadIdx.x & 31;
    if (d >= n) return;
    int k0 = g_start[d];
    int deg = g_deg[d];
    float si = g_si[d];
    float b = bptr[0];
    float ax = 0.f, ay = 0.f, az = 0.f, aw = 0.f;
#pragma unroll 4
    for (int k = k0; k < k0 + deg; k++) {
        int s = g_sorted[k];
        float z = si + g_sj[s] + b;
        float alpha = 1.0f / (1.0f + __expf(-z));
        float4 v = ((const float4*)(g_hb + (size_t)s * HID))[lane];
        ax += alpha * v.x; ay += alpha * v.y;
        az += alpha * v.z; aw += alpha * v.w;
    }
    float inv = 1.0f / (float)(deg < 1 ? 1 : deg);
    ax *= inv; ay *= inv; az *= inv; aw *= inv;
    int j = lane * 4;
    float o0 = ax * clsw[(j + 0) * 2] + ay * clsw[(j + 1) * 2] +
               az * clsw[(j + 2) * 2] + aw * clsw[(j + 3) * 2];
    float o1 = ax * clsw[(j + 0) * 2 + 1] + ay * clsw[(j + 1) * 2 + 1] +
               az * clsw[(j + 2) * 2 + 1] + aw * clsw[(j + 3) * 2 + 1];
#pragma unroll
    for (int o = 16; o; o >>= 1) {
        o0 += __shfl_xor_sync(0xFFFFFFFFu, o0, o);
        o1 += __shfl_xor_sync(0xFFFFFFFFu, o1, o);
    }
    if (lane == 0) {
        out[(size_t)d * 2 + 0] = o0 + clsb[0];
        out[(size_t)d * 2 + 1] = o1 + clsb[1];
    }
}

// ---------------------------------------------------------------------------
extern "C" void kernel_launch(void* const* d_in, const int* in_sizes, int n_in,
                              void* d_out, int out_size) {
    const float* x      = (const float*)d_in[0];
    const int*   ei     = (const int*)  d_in[1];
    const float* enc_w  = (const float*)d_in[2];
    const float* enc_b  = (const float*)d_in[3];
    const float* att1_w = (const float*)d_in[4];
    const float* att1_b = (const float*)d_in[5];
    const float* att2_w = (const float*)d_in[6];
    const float* att2_b = (const float*)d_in[7];
    const float* cls_w  = (const float*)d_in[8];
    const float* cls_b  = (const float*)d_in[9];
    float* out = (float*)d_out;

    int N = in_sizes[0] / 256;
    int E = in_sizes[1] / 2;

    // Decode edge indices (dtype-robust)
    detect64_kernel<<<1, 1024>>>(ei, 2 * E);
    convert_edges_kernel<<<(E + 255) / 256, 256>>>(ei, E);

    // CSR build (grouped by dst)
    zero_deg_kernel<<<(N + 255) / 256, 256>>>(N);
    hist_kernel<<<(E + 255) / 256, 256>>>(E);
    scan_kernel<<<1, 1024>>>(N);
    init_cursor_kernel<<<(N + 255) / 256, 256>>>(N);
    scatter_kernel<<<(E + 255) / 256, 256>>>(E);

    // Encoder
    gemm_relu_kernel<<<(N + 127) / 128, 256>>>(x, enc_w, enc_b, N);

    int node_warp_blocks = (N + 7) / 8;  // warp per node, 8 warps/block

    // Layer 1
    dots_kernel<<<node_warp_blocks, 256>>>(att1_w, N, 0);
    agg1_kernel<<<node_warp_blocks, 256>>>(att1_b, N);

    // Layer 2 (+ classifier)
    dots_kernel<<<node_warp_blocks, 256>>>(att2_w, N, 1);
    agg2_cls_kernel<<<node_warp_blocks, 256>>>(att2_b, cls_w, cls_b, out, N);
}